// round 11
// baseline (speedup 1.0000x reference)
#include <cuda_runtime.h>
#include <cuda_fp16.h>
#include <cstdint>
#include <climits>

// VQ-VAE quantizer: fp16x2 HFMA2 scan (2 MAC per fma-pipe slot) + sound margin
// + bit-exact fp32 refinement (identical arithmetic to the rel_err=0.0 round-4 path).
//
//  R10 post-mortem fix: acc[s][i][j] with runtime s forced the accumulator array
//  into local memory (LDL/STL per HFMA2 -> 16 ms). Now two NAMED arrays acc0/acc1
//  with literal indices in fully-constant unrolled bodies -> register-resident.

typedef unsigned long long u64;
typedef unsigned int u32;

#define D        64
#define NCODES   1024
#define BT       128
#define NCH      16            // chunks of 64 codes
#define CODES_CH 64
#define NBLOCKS  2048

// ---- smem byte offsets ----
#define SM_XT    0             // half2 [32 g][128 tokens]      16384
#define SM_B0    16384         // half2 [32 g][64 codes]         8192
#define SM_B1    24576         //                                8192
#define SM_SC2   32768         // f32[1024]                      4096
#define SM_M1    36864         // f32[128][8]                    4096
#define SM_M2    40960         // f32[128][8]                    4096
#define SM_I1    45056         // i32[128][8]                    4096
#define SM_MV    49152         // f32[128]                        512
#define SM_SX    49664         // f32[128]                        512
#define SM_BIDX  50176         // i32[128]                        512
#define SM_PART  50688         // u64[128]                       1024
#define SMEM_TOTAL 51712

__device__ u32   g_ch2[NCH * 32 * CODES_CH];  // fp16x2 codebook, [chunk][g][code]
__device__ float g_sumc2[NCODES];
__device__ float g_sabsb[NCODES];
__device__ float g_SBC;                        // max_k sum |b_h(k)|
__device__ float g_sc2span;
__device__ u64   g_block_loss[NBLOCKS];

__device__ __forceinline__ u32 smem_u32(const void* p) {
    u32 a; asm("{ .reg .u64 t; cvta.to.shared.u64 t, %1; cvt.u32.u64 %0, t; }" : "=r"(a) : "l"(p));
    return a;
}
__device__ __forceinline__ void cp16(u32 saddr, const void* g) {
    asm volatile("{ .reg .u64 gp; cvta.to.global.u64 gp, %1;"
                 " cp.async.cg.shared.global [%0], [gp], 16; }"
                 :: "r"(saddr), "l"(g) : "memory");
}
#define CP_COMMIT() asm volatile("cp.async.commit_group;" ::: "memory")
#define CP_WAIT1()  asm volatile("cp.async.wait_group 1;" ::: "memory")
#define CP_WAIT0()  asm volatile("cp.async.wait_group 0;" ::: "memory")

__device__ __forceinline__ __half2 as_h2(u32 v) { return *reinterpret_cast<__half2*>(&v); }

// Exact re-score: arithmetic identical to the round-4 (rel_err = 0.0) kernel.
__device__ __forceinline__ u64 exact_key(const float* __restrict__ xr,
                                         const float* __restrict__ cb,
                                         const float* __restrict__ sc2s,
                                         float sx, int ci) {
    const float* cr = cb + (size_t)ci * D;
    float dot = 0.f;
#pragma unroll 16
    for (int d = 0; d < D; d++) dot = fmaf(xr[d], cr[d], dot);
    float dist = fmaf(-2.f, dot, sx + sc2s[ci]);
    return ((u64)__float_as_uint(dist) << 32) | (u32)ci;
}

// ---------------------------------------------------------------------------
// Prep 1 (8 x 128): fp16 codebook (b = c*1024, pow-2 exact scale), sumc2
// (reference-order fma), sum|b_h|.
// ---------------------------------------------------------------------------
__global__ void prep_kernel(const float* __restrict__ cb) {
    const int k  = blockIdx.x * 128 + threadIdx.x;
    const int ch = k >> 6, j = k & 63;
    float s = 0.f, sab = 0.f;
#pragma unroll
    for (int g = 0; g < 32; g++) {
        float v0 = cb[(size_t)k * D + 2 * g];
        float v1 = cb[(size_t)k * D + 2 * g + 1];
        s = fmaf(v0, v0, s);
        s = fmaf(v1, v1, s);
        __half h0 = __float2half_rn(v0 * 1024.f);
        __half h1 = __float2half_rn(v1 * 1024.f);
        sab += fabsf(__half2float(h0)) + fabsf(__half2float(h1));
        __half2 p = __halves2half2(h0, h1);
        g_ch2[(ch * 32 + g) * CODES_CH + j] = *reinterpret_cast<u32*>(&p);
    }
    g_sumc2[k] = s;
    g_sabsb[k] = sab;
}

// ---------------------------------------------------------------------------
// Prep 2 (1 x 256): SBC = max sum|b|, sc2 span.
// ---------------------------------------------------------------------------
__global__ void prep2_kernel() {
    __shared__ float ra[256], rb[256], rc[256];
    const int t = threadIdx.x;
    float ma = -1e30f, mb = -1e30f, mc = 1e30f;
    for (int i = t; i < NCODES; i += 256) {
        ma = fmaxf(ma, g_sabsb[i]);
        float s = g_sumc2[i];
        mb = fmaxf(mb, s);
        mc = fminf(mc, s);
    }
    ra[t] = ma; rb[t] = mb; rc[t] = mc;
    __syncthreads();
    for (int st = 128; st > 0; st >>= 1) {
        if (t < st) {
            ra[t] = fmaxf(ra[t], ra[t + st]);
            rb[t] = fmaxf(rb[t], rb[t + st]);
            rc[t] = fminf(rc[t], rc[t + st]);
        }
        __syncthreads();
    }
    if (t == 0) { g_SBC = ra[0]; g_sc2span = rb[0] - rc[0]; }
}

// ---------------------------------------------------------------------------
// Main kernel: 256 threads, 128 tokens/block. ty=tid>>3 owns 4 tokens,
// tx=tid&7 owns 8 codes per 64-code chunk (=> 8 columns of 128 codes/token).
// ---------------------------------------------------------------------------
__global__ __launch_bounds__(256, 2)
void vq_kernel(const float* __restrict__ x,
               const float* __restrict__ cb,
               float* __restrict__ out_q,
               float* __restrict__ out_idx) {
    extern __shared__ char smem[];
    const u32 sb  = smem_u32(smem);          // shared-space addr: cp.async ONLY
    const int tid = threadIdx.x;
    const int t0  = blockIdx.x * BT;

    float* sc2s = (float*)(smem + SM_SC2);
    float* M1s  = (float*)(smem + SM_M1);
    float* M2s  = (float*)(smem + SM_M2);
    int*   I1s  = (int*)(smem + SM_I1);
    float* MVs  = (float*)(smem + SM_MV);
    float* SXs  = (float*)(smem + SM_SX);
    int*   bidx = (int*)(smem + SM_BIDX);
    u64*   part = (u64*)(smem + SM_PART);

    // Prefetch code chunk 0 (8 KB)
    for (u32 off = tid * 16; off < 32 * CODES_CH * 4; off += 256 * 16)
        cp16(sb + SM_B0 + off, (const char*)g_ch2 + off);
    CP_COMMIT();

    for (int i = tid; i < NCODES; i += 256) sc2s[i] = g_sumc2[i];

    // Per-token prologue (tid < 128): exact sx (ref order), stats, fp16 tile, margin
    if (tid < BT) {
        const float* xr = x + (size_t)(t0 + tid) * D;
        float xmax = 1e-30f, s1 = 0.f, sx = 0.f;
#pragma unroll 16
        for (int d = 0; d < D; d++) {
            float v = xr[d];
            sx = fmaf(v, v, sx);
            float a = fabsf(v);
            xmax = fmaxf(xmax, a);
            s1 += a;
        }
        SXs[tid] = sx;
        const float inv = 1.f / xmax;
#pragma unroll
        for (int g = 0; g < 32; g++) {
            __half2 p = __halves2half2(__float2half_rn(xr[2 * g] * inv),
                                       __float2half_rn(xr[2 * g + 1] * inv));
            *(u32*)(smem + SM_XT + g * 512 + tid * 4) = *reinterpret_cast<u32*>(&p);
        }
        // Sound margin in v units. Two 16-step fp16 chains per pair; running sums
        // bounded by P; per-op err <= ulp16(P+0.75)/2; input cvt err 2^-11*(S1x+SBC).
        const float S1x = s1 * inv;
        const float SBC = g_SBC;
        float P  = fminf(S1x * 1.01f + 0.1f, SBC * 1.01f + 0.1f);
        float u  = exp2f(floorf(log2f(P + 0.75f)) - 10.f);
        float E  = 32.f * u + 4.8828e-4f * (S1x + SBC) + 2e-3f;
        MVs[tid] = 2.f * E + (g_sc2span + 4e-5f) * (1024.f / (2.f * xmax)) + 0.02f;
    }

    const int ty = tid >> 3, tx = tid & 7;
    const char* a_base = smem + SM_XT + ty * 16;      // + g*512 (generic ptr, LDS.128)
    const int   b_off  = tx * 32;                     // + g*256 within buffer

    float m1[4], m2[4];
    int   i1[4];
#pragma unroll
    for (int i = 0; i < 4; i++) { m1[i] = -3.4e38f; m2[i] = -3.4e38f; i1[i] = 0; }

    for (int ch = 0; ch < NCH; ch++) {
        if (ch + 1 < NCH) {   // prefetch next chunk into other buffer
            const u32 dst = sb + (((ch + 1) & 1) ? SM_B1 : SM_B0);
            const char* src = (const char*)g_ch2 + (size_t)(ch + 1) * 8192;
            for (u32 off = tid * 16; off < 8192; off += 256 * 16)
                cp16(dst + off, src + off);
            CP_COMMIT();
            CP_WAIT1();       // current chunk's group complete
        } else {
            CP_WAIT0();
        }
        __syncthreads();      // publish copies (and, ch=0: x tile) to all threads

        const char* b_base = smem + (((ch & 1) ? SM_B1 : SM_B0) + b_off);

        // Two named accumulator banks, ONLY literal indices (register-resident).
        __half2 acc0[4][8], acc1[4][8];
#pragma unroll
        for (int i = 0; i < 4; i++)
#pragma unroll
            for (int j = 0; j < 8; j++) {
                acc0[i][j] = __float2half2_rn(0.f);
                acc1[i][j] = __float2half2_rn(0.f);
            }

#pragma unroll 4
        for (int g2 = 0; g2 < 16; g2++) {
            {   // even dim-pair group g = 2*g2 -> chain 0
                const uint4 av  = *(const uint4*)(a_base + (2 * g2) * 512);
                const uint4 bv0 = *(const uint4*)(b_base + (2 * g2) * 256);
                const uint4 bv1 = *(const uint4*)(b_base + (2 * g2) * 256 + 16);
                __half2 ah[4] = {as_h2(av.x), as_h2(av.y), as_h2(av.z), as_h2(av.w)};
                __half2 bh[8] = {as_h2(bv0.x), as_h2(bv0.y), as_h2(bv0.z), as_h2(bv0.w),
                                 as_h2(bv1.x), as_h2(bv1.y), as_h2(bv1.z), as_h2(bv1.w)};
#pragma unroll
                for (int i = 0; i < 4; i++)
#pragma unroll
                    for (int j = 0; j < 8; j++)
                        acc0[i][j] = __hfma2(ah[i], bh[j], acc0[i][j]);
            }
            {   // odd dim-pair group g = 2*g2+1 -> chain 1
                const uint4 av  = *(const uint4*)(a_base + (2 * g2 + 1) * 512);
                const uint4 bv0 = *(const uint4*)(b_base + (2 * g2 + 1) * 256);
                const uint4 bv1 = *(const uint4*)(b_base + (2 * g2 + 1) * 256 + 16);
                __half2 ah[4] = {as_h2(av.x), as_h2(av.y), as_h2(av.z), as_h2(av.w)};
                __half2 bh[8] = {as_h2(bv0.x), as_h2(bv0.y), as_h2(bv0.z), as_h2(bv0.w),
                                 as_h2(bv1.x), as_h2(bv1.y), as_h2(bv1.z), as_h2(bv1.w)};
#pragma unroll
                for (int i = 0; i < 4; i++)
#pragma unroll
                    for (int j = 0; j < 8; j++)
                        acc1[i][j] = __hfma2(ah[i], bh[j], acc1[i][j]);
            }
        }

        // Finalize chunk: fp32 combine (fixed order) + per-(token,column) top-2
        const int cbase = ch * CODES_CH + tx * 8;
#pragma unroll
        for (int i = 0; i < 4; i++)
#pragma unroll
            for (int j = 0; j < 8; j++) {
                float v = ((__low2float(acc0[i][j]) + __high2float(acc0[i][j]))
                           + __low2float(acc1[i][j])) + __high2float(acc1[i][j]);
                if (v > m2[i]) {
                    if (v > m1[i]) { m2[i] = m1[i]; m1[i] = v; i1[i] = cbase + j; }
                    else           { m2[i] = v; }
                }
            }
        __syncthreads();   // buffer fully consumed before next iter's prefetch reuses it
    }

#pragma unroll
    for (int i = 0; i < 4; i++) {
        const int t = ty * 4 + i;
        M1s[t * 8 + tx] = m1[i];
        M2s[t * 8 + tx] = m2[i];
        I1s[t * 8 + tx] = i1[i];
    }
    __syncthreads();

    // ---- Refinement (token = tid < 128) ----
    if (tid < BT) {
        const int t = tid;
        float gm = -3.4e38f;
#pragma unroll
        for (int c = 0; c < 8; c++) gm = fmaxf(gm, M1s[t * 8 + c]);
        const float thr = gm - MVs[t];

        const float* xr = x + (size_t)(t0 + t) * D;
        const float  sx = SXs[t];
        u64 best = 0xFFFFFFFFFFFFFFFFull;
        for (int c = 0; c < 8; c++) {
            if (M1s[t * 8 + c] < thr) continue;
            if (M2s[t * 8 + c] >= thr) {
                // >=2 in-margin codes in this 128-code column: exact-rescore it all
                // (any deeper in-margin code forces m2 >= thr, so this is sound).
                for (int ch2 = 0; ch2 < NCH; ch2++) {
                    const int kb = ch2 * CODES_CH + c * 8;
#pragma unroll
                    for (int j = 0; j < 8; j++) {
                        u64 key = exact_key(xr, cb, sc2s, sx, kb + j);
                        if (key < best) best = key;
                    }
                }
            } else {
                u64 key = exact_key(xr, cb, sc2s, sx, I1s[t * 8 + c]);
                if (key < best) best = key;
            }
        }

        const int   besti = (int)(best & 0xFFFFFFFFull);
        const float bestd = __uint_as_float((u32)(best >> 32));
        bidx[t] = besti;
        out_idx[t0 + t] = (float)besti;
        part[t] = (u64)llrintf(bestd * 1073741824.f);   // Q30 fixed point
    }
    __syncthreads();

    if (tid == 0) {
        u64 s = 0;
        for (int k = 0; k < BT; k++) s += part[k];
        g_block_loss[blockIdx.x] = s;                   // fresh write: deterministic
    }

    // Quantized output, coalesced; straight-through rounding x + (q - x)
    for (int idx = tid; idx < BT * D; idx += 256) {
        int t = idx >> 6, d = idx & 63;
        float q  = __ldg(&cb[(size_t)bidx[t] * D + d]);
        float xv = x[(size_t)(t0 + t) * D + d];
        out_q[(size_t)(t0 + t) * D + d] = xv + (q - xv);
    }
}

// ---------------------------------------------------------------------------
// Finalize: loss = m + 0.25*m, m = mean(best_dist) over N*D elements
// ---------------------------------------------------------------------------
__global__ void finalize_kernel(float* __restrict__ out_loss, double inv_count) {
    __shared__ u64 sh[256];
    u64 s = 0;
    for (int i = threadIdx.x; i < NBLOCKS; i += 256) s += g_block_loss[i];
    sh[threadIdx.x] = s;
    __syncthreads();
    for (int st = 128; st > 0; st >>= 1) {
        if (threadIdx.x < st) sh[threadIdx.x] += sh[threadIdx.x + st];
        __syncthreads();
    }
    if (threadIdx.x == 0) {
        double tot = (double)sh[0] * (1.0 / 1073741824.0);
        float  m   = (float)(tot * inv_count);
        out_loss[0] = m + 0.25f * m;
    }
}

extern "C" void kernel_launch(void* const* d_in, const int* in_sizes, int n_in,
                              void* d_out, int out_size) {
    const float* x  = (const float*)d_in[0];
    const float* cb = (const float*)d_in[1];
    float* out = (float*)d_out;

    const int n = in_sizes[0] / D;            // 262144 tokens
    float* out_q    = out;
    float* out_loss = out + (size_t)n * D;
    float* out_idx  = out_loss + 1;

    cudaFuncSetAttribute(vq_kernel, cudaFuncAttributeMaxDynamicSharedMemorySize,
                         SMEM_TOTAL);

    prep_kernel<<<8, 128>>>(cb);
    prep2_kernel<<<1, 256>>>();
    vq_kernel<<<n / BT, 256, SMEM_TOTAL>>>(x, cb, out_q, out_idx);
    finalize_kernel<<<1, 256>>>(out_loss, 1.0 / ((double)n * D));
}

// round 15
// speedup vs baseline: 5.9969x; 5.9969x over previous
#include <cuda_runtime.h>
#include <cstdint>
#include <climits>

// VQ-VAE quantizer — dual-pipe hybrid scan:
//   codes   0..511 : exact fp32 FFMA distances (verbatim round-4 pipeline, rel_err=0.0)
//   codes 512..1023: exact-int8 dp4a scan + sound margin (verbatim round-8 machinery)
// Even/odd warps run the two phases in opposite order so the fp32-FMA pipe and the
// integer-dot path are fed simultaneously. All final decisions (argmin, loss,
// quantized) go through the exact fp32 pipeline -> bit-identical to the reference.

typedef unsigned long long u64;
typedef unsigned int u32;

#define D        64
#define NCODES   1024
#define BT       128
#define NBLOCKS  2048
#define SC_INV   130048.f          // 1/s_c = 1024*127
#define SC_VAL   (1.f/130048.f)
#define BSTRIDE  132               // fp32 code-tile row stride (floats)

// ---- smem byte offsets ----
#define SM_AS    0                  // f32 [64 d][132] tokens (transposed)   33792
#define SM_B0    33792              // f32 [64 d][132] code chunk buf0       33792
#define SM_B1    67584              //                                        33792
#define SM_CQ    101376             // u32 [16 g][512] int8 codes 512..1023  32768
#define SM_XQ    134144             // u32 [16 g][128] int8 tokens            8192
#define SM_SC2   142336             // f32 [1024]                             4096
#define SM_MS    146432             // i32 [128]                               512
#define SM_SX    146944             // f32 [128]                               512
#define SM_BIDX  147456             // i32 [128]                               512
#define SM_PART  147968             // u64 [128]                              1024
#define SMEM_TOTAL 148992

__device__ float g_bt[4 * D * BSTRIDE];     // fp32 codes 0..511, [ch][d][132]
__device__ u32   g_cq[16 * 512];            // int8 codes 512..1023, [g][code-512]
__device__ float g_sumc2[NCODES];
__device__ float g_sabs[NCODES];
__device__ float g_sacmax;
__device__ float g_sc2span;
__device__ u64   g_block_loss[NBLOCKS];

__device__ __forceinline__ u32 smem_u32(const void* p) {
    u32 a; asm("{ .reg .u64 t; cvta.to.shared.u64 t, %1; cvt.u32.u64 %0, t; }" : "=r"(a) : "l"(p));
    return a;
}
__device__ __forceinline__ void cp16(u32 saddr, const void* g) {
    asm volatile("{ .reg .u64 gp; cvta.to.global.u64 gp, %1;"
                 " cp.async.cg.shared.global [%0], [gp], 16; }"
                 :: "r"(saddr), "l"(g) : "memory");
}
#define CP_COMMIT() asm volatile("cp.async.commit_group;" ::: "memory")
#define CP_WAIT1()  asm volatile("cp.async.wait_group 1;" ::: "memory")
#define CP_WAIT0()  asm volatile("cp.async.wait_group 0;" ::: "memory")

__device__ __forceinline__ int clamp127(int v) {
    return v > 127 ? 127 : (v < -127 ? -127 : v);
}
__device__ __forceinline__ u32 pack4(int a0, int a1, int a2, int a3) {
    return (u32)(a0 & 0xFF) | ((u32)(a1 & 0xFF) << 8) |
           ((u32)(a2 & 0xFF) << 16) | ((u32)(a3 & 0xFF) << 24);
}

// Exact re-score: arithmetic identical to the round-4 (rel_err = 0.0) kernel.
__device__ __noinline__ u64 exact_key(const float* __restrict__ xr,
                                      const float* __restrict__ cb,
                                      const float* __restrict__ sc2s,
                                      float sx, int ci) {
    const float* cr = cb + (size_t)ci * D;
    float dot = 0.f;
#pragma unroll 16
    for (int d = 0; d < D; d++) dot = fmaf(xr[d], cr[d], dot);
    float dist = fmaf(-2.f, dot, sx + sc2s[ci]);
    return ((u64)__float_as_uint(dist) << 32) | (u32)ci;
}

// ---------------------------------------------------------------------------
// Prep 1 (8 x 128): sumc2 (ref-order fma) + sum|c|; codes 0..511 -> fp32
// transposed tiles; codes 512..1023 -> packed int8 [g][code].
// ---------------------------------------------------------------------------
__global__ void prep_kernel(const float* __restrict__ cb) {
    const int k = blockIdx.x * 128 + threadIdx.x;
    float v[D];
    float s = 0.f, sa = 0.f;
#pragma unroll 16
    for (int d = 0; d < D; d++) {
        float c = cb[(size_t)k * D + d];
        v[d] = c;
        s = fmaf(c, c, s);
        sa += fabsf(c);
    }
    g_sumc2[k] = s;
    g_sabs[k]  = sa;
    if (k < 512) {
        const int ch = k >> 7, c = k & 127;
#pragma unroll 16
        for (int d = 0; d < D; d++)
            g_bt[(ch * D + d) * BSTRIDE + c] = v[d];
    } else {
        const int j = k - 512;
#pragma unroll
        for (int g = 0; g < 16; g++)
            g_cq[g * 512 + j] = pack4(
                clamp127(__float2int_rn(v[4 * g + 0] * SC_INV)),
                clamp127(__float2int_rn(v[4 * g + 1] * SC_INV)),
                clamp127(__float2int_rn(v[4 * g + 2] * SC_INV)),
                clamp127(__float2int_rn(v[4 * g + 3] * SC_INV)));
    }
}

// ---------------------------------------------------------------------------
// Prep 2 (1 x 256): SACmax + sc2 span (for the sound dp4a margin).
// ---------------------------------------------------------------------------
__global__ void prep2_kernel() {
    __shared__ float ra[256], rb[256], rc[256];
    const int t = threadIdx.x;
    float ma = -1e30f, mb = -1e30f, mc = 1e30f;
    for (int i = t; i < NCODES; i += 256) {
        ma = fmaxf(ma, g_sabs[i]);
        float s = g_sumc2[i];
        mb = fmaxf(mb, s);
        mc = fminf(mc, s);
    }
    ra[t] = ma; rb[t] = mb; rc[t] = mc;
    __syncthreads();
    for (int st = 128; st > 0; st >>= 1) {
        if (t < st) {
            ra[t] = fmaxf(ra[t], ra[t + st]);
            rb[t] = fmaxf(rb[t], rb[t + st]);
            rc[t] = fminf(rc[t], rc[t + st]);
        }
        __syncthreads();
    }
    if (t == 0) { g_sacmax = ra[0]; g_sc2span = rb[0] - rc[0]; }
}

// ---- scan phase macros (register arrays only ever literal-indexed) ----

#define FFMA_PHASE()                                                            \
    do {                                                                        \
        float acc[8][8];                                                        \
        _Pragma("unroll")                                                       \
        for (int i = 0; i < 8; i++)                                             \
            _Pragma("unroll")                                                   \
            for (int j = 0; j < 8; j++) acc[i][j] = 0.f;                        \
        const float* Ap = (const float*)(smem + SM_AS) + ty * 8;                \
        const float* Bp = Bsp + tx * 8;                                         \
        _Pragma("unroll 4")                                                     \
        for (int d = 0; d < D; d++) {                                           \
            float4 a0 = *(const float4*)(Ap + d * BSTRIDE);                     \
            float4 a1 = *(const float4*)(Ap + d * BSTRIDE + 4);                 \
            float4 b0 = *(const float4*)(Bp + d * BSTRIDE);                     \
            float4 b1 = *(const float4*)(Bp + d * BSTRIDE + 4);                 \
            float a[8] = {a0.x, a0.y, a0.z, a0.w, a1.x, a1.y, a1.z, a1.w};      \
            float b[8] = {b0.x, b0.y, b0.z, b0.w, b1.x, b1.y, b1.z, b1.w};      \
            _Pragma("unroll")                                                   \
            for (int i = 0; i < 8; i++)                                         \
                _Pragma("unroll")                                               \
                for (int j = 0; j < 8; j++)                                     \
                    acc[i][j] = fmaf(a[i], b[j], acc[i][j]);                    \
        }                                                                       \
        const int c0 = ch * 128 + tx * 8;                                       \
        _Pragma("unroll")                                                       \
        for (int i = 0; i < 8; i++) {                                           \
            const float sxi = SXs[ty * 8 + i];                                  \
            _Pragma("unroll")                                                   \
            for (int j = 0; j < 8; j++) {                                       \
                float dist = fmaf(-2.f, acc[i][j], sxi + sc2s[c0 + j]);         \
                if (dist < fbd[i]) { fbd[i] = dist; fbi[i] = c0 + j; }          \
            }                                                                   \
        }                                                                       \
    } while (0)

#define DP4A_PHASE()                                                            \
    do {                                                                        \
        int acci[8][8];                                                         \
        _Pragma("unroll")                                                       \
        for (int i = 0; i < 8; i++)                                             \
            _Pragma("unroll")                                                   \
            for (int j = 0; j < 8; j++) acci[i][j] = 0;                         \
        const u32* Xq = (const u32*)(smem + SM_XQ) + ty * 8;                    \
        const u32* Cq = (const u32*)(smem + SM_CQ) + ch * 128 + tx * 8;         \
        _Pragma("unroll")                                                       \
        for (int g = 0; g < 16; g++) {                                          \
            uint4 xa0 = *(const uint4*)(Xq + g * 128);                          \
            uint4 xa1 = *(const uint4*)(Xq + g * 128 + 4);                      \
            uint4 cv0 = *(const uint4*)(Cq + g * 512);                          \
            uint4 cv1 = *(const uint4*)(Cq + g * 512 + 4);                      \
            u32 xa[8] = {xa0.x, xa0.y, xa0.z, xa0.w, xa1.x, xa1.y, xa1.z, xa1.w};\
            u32 cv[8] = {cv0.x, cv0.y, cv0.z, cv0.w, cv1.x, cv1.y, cv1.z, cv1.w};\
            _Pragma("unroll")                                                   \
            for (int i = 0; i < 8; i++)                                         \
                _Pragma("unroll")                                               \
                for (int j = 0; j < 8; j++)                                     \
                    acci[i][j] = __dp4a((int)xa[i], (int)cv[j], acci[i][j]);    \
        }                                                                       \
        const int d0 = 512 + ch * 128 + tx * 8;                                 \
        _Pragma("unroll")                                                       \
        for (int i = 0; i < 8; i++)                                             \
            _Pragma("unroll")                                                   \
            for (int j = 0; j < 8; j++) {                                       \
                int v = acci[i][j];                                             \
                if (v > m2[i]) {                                                \
                    if (v > m1[i]) { m2[i] = m1[i]; m1[i] = v; i1[i] = d0 + j; }\
                    else           { m2[i] = v; }                               \
                }                                                               \
            }                                                                   \
    } while (0)

// ---------------------------------------------------------------------------
// Main kernel: 256 threads, 128 tokens/block. ty=tid>>4 owns 8 tokens,
// tx=tid&15 owns 8 FFMA codes + 8 dp4a codes per chunk (4 chunks each half).
// ---------------------------------------------------------------------------
__global__ __launch_bounds__(256)
void vq_kernel(const float* __restrict__ x,
               const float* __restrict__ cb,
               float* __restrict__ out_q,
               float* __restrict__ out_idx) {
    extern __shared__ char smem[];
    const u32 sb  = smem_u32(smem);          // shared-space addr for cp.async ONLY
    const int tid = threadIdx.x;
    const int t0  = blockIdx.x * BT;

    float* sc2s = (float*)(smem + SM_SC2);
    int*   Ms   = (int*)(smem + SM_MS);
    float* SXs  = (float*)(smem + SM_SX);
    int*   bidx = (int*)(smem + SM_BIDX);
    u64*   part = (u64*)(smem + SM_PART);

    // Group 0: int8 codes (32KB) + fp32 code chunk 0 (33792B)
    for (u32 off = tid * 16; off < 16 * 512 * 4; off += 256 * 16)
        cp16(sb + SM_CQ + off, (const char*)g_cq + off);
    for (u32 off = tid * 16; off < D * BSTRIDE * 4; off += 256 * 16)
        cp16(sb + SM_B0 + off, (const char*)g_bt + off);
    CP_COMMIT();

    for (int i = tid; i < NCODES; i += 256) sc2s[i] = g_sumc2[i];

    // Per-token prologue (tid < 128): exact sx, stats, As (conflict-free STS),
    // int8 pack, sound dp4a margin (round-8 formula, validated).
    if (tid < BT) {
        const float* xr = x + (size_t)(t0 + tid) * D;
        float v[D];
        float xmax = 1e-30f, s1 = 0.f, sx = 0.f;
#pragma unroll 16
        for (int d = 0; d < D; d++) {
            float c = xr[d];
            v[d] = c;
            sx = fmaf(c, c, sx);
            float a = fabsf(c);
            xmax = fmaxf(xmax, a);
            s1 += a;
        }
        SXs[tid] = sx;
        float* As = (float*)(smem + SM_AS);
#pragma unroll 16
        for (int d = 0; d < D; d++) As[d * BSTRIDE + tid] = v[d];
        const float inv = 127.f / xmax;
        u32* xq = (u32*)(smem + SM_XQ);
#pragma unroll
        for (int g = 0; g < 16; g++)
            xq[g * 128 + tid] = pack4(
                clamp127(__float2int_rn(v[4 * g + 0] * inv)),
                clamp127(__float2int_rn(v[4 * g + 1] * inv)),
                clamp127(__float2int_rn(v[4 * g + 2] * inv)),
                clamp127(__float2int_rn(v[4 * g + 3] * inv)));
        const float s_x = xmax / 127.f;
        float e_q    = 0.5f * SC_VAL * s1 + 0.5f * s_x * g_sacmax
                     + 16.f * s_x * SC_VAL;
        float M_dist = g_sc2span + 4.f * e_q + 4e-5f;
        Ms[tid] = (int)ceilf(M_dist / (2.f * s_x * SC_VAL)) + 8;
    }

    const int ty = tid >> 4, tx = tid & 15;
    const int wodd = (tid >> 5) & 1;

    float fbd[8];
    int   fbi[8], m1[8], m2[8], i1[8];
#pragma unroll
    for (int i = 0; i < 8; i++) {
        fbd[i] = 3.4e38f; fbi[i] = 0;
        m1[i] = INT_MIN;  m2[i] = INT_MIN; i1[i] = 512;
    }

    for (int ch = 0; ch < 4; ch++) {
        if (ch < 3) {   // prefetch next fp32 code chunk into the other buffer
            const u32 dst = sb + (((ch + 1) & 1) ? SM_B1 : SM_B0);
            const char* src = (const char*)g_bt + (size_t)(ch + 1) * D * BSTRIDE * 4;
            for (u32 off = tid * 16; off < D * BSTRIDE * 4; off += 256 * 16)
                cp16(dst + off, src + off);
            CP_COMMIT();
            CP_WAIT1();
        } else {
            CP_WAIT0();
        }
        __syncthreads();

        const float* Bsp = (const float*)(smem + ((ch & 1) ? SM_B1 : SM_B0));

        // Phase swap: half the warps feed the FMA pipe while the other half
        // feeds the integer-dot path, then they exchange.
        if (wodd) { DP4A_PHASE(); FFMA_PHASE(); }
        else      { FFMA_PHASE(); DP4A_PHASE(); }

        __syncthreads();   // buffers fully consumed before next prefetch reuses them
    }

    // ---- Finale: dp4a margin-refine + merge with exact FFMA half ----
    const float* cbp = cb;
#pragma unroll 1
    for (int i = 0; i < 8; i++) {
        const int t = ty * 8 + i;
        // dp4a-side gmax across the 16 columns of this token (half-warp)
        int g = m1[i];
#pragma unroll
        for (int k = 8; k > 0; k >>= 1)
            g = max(g, __shfl_xor_sync(0xffffffffu, g, k, 16));
        const int thr = g - Ms[t];

        const float* xr = x + (size_t)(t0 + t) * D;
        const float  sx = SXs[t];
        u64 best = ((u64)__float_as_uint(fbd[i]) << 32) | (u32)fbi[i];
        if (m1[i] >= thr) {
            u64 k1 = exact_key(xr, cbp, sc2s, sx, i1[i]);
            if (k1 < best) best = k1;
        }
        if (m2[i] >= thr) {
            // rare: >=2 in-margin dp4a codes in this 32-code column -> exact all
#pragma unroll 1
            for (int ch2 = 0; ch2 < 4; ch2++)
#pragma unroll 1
                for (int j = 0; j < 8; j++) {
                    u64 k2 = exact_key(xr, cbp, sc2s, sx, 512 + ch2 * 128 + tx * 8 + j);
                    if (k2 < best) best = k2;
                }
        }
        // half-warp u64 key min (exact first-index tie-break)
#pragma unroll
        for (int k = 8; k > 0; k >>= 1) {
            u64 o = __shfl_xor_sync(0xffffffffu, best, k, 16);
            if (o < best) best = o;
        }
        if (tx == 0) {
            const int   besti = (int)(best & 0xFFFFFFFFull);
            const float bestd = __uint_as_float((u32)(best >> 32));
            bidx[t] = besti;
            out_idx[t0 + t] = (float)besti;
            part[t] = (u64)llrintf(bestd * 1073741824.f);   // Q30 fixed point
        }
    }
    __syncthreads();

    if (tid == 0) {
        u64 s = 0;
        for (int k = 0; k < BT; k++) s += part[k];
        g_block_loss[blockIdx.x] = s;                       // fresh write: deterministic
    }

    // Quantized output, coalesced; straight-through rounding x + (q - x)
    for (int idx = tid; idx < BT * D; idx += 256) {
        int t = idx >> 6, d = idx & 63;
        float q  = __ldg(&cb[(size_t)bidx[t] * D + d]);
        float xv = x[(size_t)(t0 + t) * D + d];
        out_q[(size_t)(t0 + t) * D + d] = xv + (q - xv);
    }
}

// ---------------------------------------------------------------------------
// Finalize: loss = m + 0.25*m, m = mean(best_dist) over N*D elements
// ---------------------------------------------------------------------------
__global__ void finalize_kernel(float* __restrict__ out_loss, double inv_count) {
    __shared__ u64 sh[256];
    u64 s = 0;
    for (int i = threadIdx.x; i < NBLOCKS; i += 256) s += g_block_loss[i];
    sh[threadIdx.x] = s;
    __syncthreads();
    for (int st = 128; st > 0; st >>= 1) {
        if (threadIdx.x < st) sh[threadIdx.x] += sh[threadIdx.x + st];
        __syncthreads();
    }
    if (threadIdx.x == 0) {
        double tot = (double)sh[0] * (1.0 / 1073741824.0);
        float  m   = (float)(tot * inv_count);
        out_loss[0] = m + 0.25f * m;
    }
}

extern "C" void kernel_launch(void* const* d_in, const int* in_sizes, int n_in,
                              void* d_out, int out_size) {
    const float* x  = (const float*)d_in[0];
    const float* cb = (const float*)d_in[1];
    float* out = (float*)d_out;

    const int n = in_sizes[0] / D;            // 262144 tokens
    float* out_q    = out;
    float* out_loss = out + (size_t)n * D;
    float* out_idx  = out_loss + 1;

    cudaFuncSetAttribute(vq_kernel, cudaFuncAttributeMaxDynamicSharedMemorySize,
                         SMEM_TOTAL);

    prep_kernel<<<8, 128>>>(cb);
    prep2_kernel<<<1, 256>>>();
    vq_kernel<<<n / BT, 256, SMEM_TOTAL>>>(x, cb, out_q, out_idx);
    finalize_kernel<<<1, 256>>>(out_loss, 1.0 / ((double)n * D));
}

// round 16
// speedup vs baseline: 11.7848x; 1.9651x over previous
#include <cuda_runtime.h>
#include <cstdint>
#include <climits>

// VQ-VAE quantizer: exact-int8 dp4a scan + sound margin + bit-exact fp32 refinement.
// IDENTICAL to the round-8 kernel (passed, rel_err = 0.0, 1088 us) except the
// __launch_bounds__ occupancy cap is removed: R8 ran under a 128-register cap with
// ~125+ live registers in the scan -> spills. Without the cap ptxas allocates
// freely (occupancy 1, 8 warps/SM) and the 64-chain dp4a scan stays in registers.

typedef unsigned long long u64;
typedef unsigned int u32;

#define D        64
#define NCODES   1024
#define BT       128
#define NBLOCKS  2048
#define SC_INV   130048.f          // 1/s_c = 1024*127 (codes: |c| <= 1/1024)
#define SC_VAL   (1.f/130048.f)

// ---- smem byte offsets ----
#define SM_CQ    0                 // u32[16][1024] packed int8 codes   65536
#define SM_XQ    65536             // u32[16][128]  packed int8 tokens   8192
#define SM_M1    73728             // i32[128][16]                       8192
#define SM_M2    81920             // i32[128][16]                       8192
#define SM_I1    90112             // i32[128][16]                       8192
#define SM_SC2   98304             // f32[1024]                          4096
#define SM_MS    102400            // i32[128]                            512
#define SM_SX    102912            // f32[128]                            512
#define SM_BIDX  103424            // i32[128]                            512
#define SM_PART  103936            // u64[128]                           1024
#define SMEM_TOTAL 104960

__device__ u32   g_cq[16 * NCODES];   // packed int8 codes, [dim-group][code]
__device__ float g_sumc2[NCODES];
__device__ float g_sabs[NCODES];
__device__ float g_sacmax;            // max_k sum|c_k|
__device__ float g_sc2span;           // max-min sumc2
__device__ u64   g_block_loss[NBLOCKS];

__device__ __forceinline__ u32 smem_u32(const void* p) {
    u32 a; asm("{ .reg .u64 t; cvta.to.shared.u64 t, %1; cvt.u32.u64 %0, t; }" : "=r"(a) : "l"(p));
    return a;
}
__device__ __forceinline__ void cp16(u32 saddr, const void* g) {
    asm volatile("{ .reg .u64 gp; cvta.to.global.u64 gp, %1;"
                 " cp.async.cg.shared.global [%0], [gp], 16; }"
                 :: "r"(saddr), "l"(g) : "memory");
}
#define CP_COMMIT() asm volatile("cp.async.commit_group;" ::: "memory")
#define CP_WAIT0()  asm volatile("cp.async.wait_group 0;" ::: "memory")

__device__ __forceinline__ int clamp127(int v) {
    return v > 127 ? 127 : (v < -127 ? -127 : v);
}
__device__ __forceinline__ u32 pack4(int a0, int a1, int a2, int a3) {
    return (u32)(a0 & 0xFF) | ((u32)(a1 & 0xFF) << 8) |
           ((u32)(a2 & 0xFF) << 16) | ((u32)(a3 & 0xFF) << 24);
}

// Exact re-score: arithmetic identical to the round-4 (rel_err = 0.0) kernel.
__device__ __forceinline__ u64 exact_key(const float* __restrict__ xr,
                                         const float* __restrict__ cb,
                                         const float* __restrict__ sc2s,
                                         float sx, int ci) {
    const float* cr = cb + (size_t)ci * D;
    float dot = 0.f;
#pragma unroll 16
    for (int d = 0; d < D; d++) dot = fmaf(xr[d], cr[d], dot);
    float dist = fmaf(-2.f, dot, sx + sc2s[ci]);
    return ((u64)__float_as_uint(dist) << 32) | (u32)ci;
}

// ---------------------------------------------------------------------------
// Prep 1 (grid 8 x 128): quantize codebook, exact sumc2 (ref-order fma), sum|c|.
// ---------------------------------------------------------------------------
__global__ void prep_kernel(const float* __restrict__ cb) {
    const int k = blockIdx.x * 128 + threadIdx.x;
    float s = 0.f, sa = 0.f;
#pragma unroll
    for (int g = 0; g < 16; g++) {
        float v0 = cb[(size_t)k * D + 4 * g + 0];
        float v1 = cb[(size_t)k * D + 4 * g + 1];
        float v2 = cb[(size_t)k * D + 4 * g + 2];
        float v3 = cb[(size_t)k * D + 4 * g + 3];
        s = fmaf(v0, v0, s); s = fmaf(v1, v1, s);
        s = fmaf(v2, v2, s); s = fmaf(v3, v3, s);
        sa += fabsf(v0) + fabsf(v1) + fabsf(v2) + fabsf(v3);
        g_cq[g * NCODES + k] = pack4(
            clamp127(__float2int_rn(v0 * SC_INV)),
            clamp127(__float2int_rn(v1 * SC_INV)),
            clamp127(__float2int_rn(v2 * SC_INV)),
            clamp127(__float2int_rn(v3 * SC_INV)));
    }
    g_sumc2[k] = s;
    g_sabs[k]  = sa;
}

// ---------------------------------------------------------------------------
// Prep 2 (1 x 256): reductions for the sound margin.
// ---------------------------------------------------------------------------
__global__ void prep2_kernel() {
    __shared__ float ra[256], rb[256], rc[256];
    const int t = threadIdx.x;
    float ma = -1e30f, mb = -1e30f, mc = 1e30f;
    for (int i = t; i < NCODES; i += 256) {
        ma = fmaxf(ma, g_sabs[i]);
        float s = g_sumc2[i];
        mb = fmaxf(mb, s);
        mc = fminf(mc, s);
    }
    ra[t] = ma; rb[t] = mb; rc[t] = mc;
    __syncthreads();
    for (int st = 128; st > 0; st >>= 1) {
        if (t < st) {
            ra[t] = fmaxf(ra[t], ra[t + st]);
            rb[t] = fmaxf(rb[t], rb[t + st]);
            rc[t] = fminf(rc[t], rc[t + st]);
        }
        __syncthreads();
    }
    if (t == 0) { g_sacmax = ra[0]; g_sc2span = rb[0] - rc[0]; }
}

// ---------------------------------------------------------------------------
// Main kernel: 256 threads, 128 tokens/block. ty=tid>>4 owns 8 tokens,
// tx=tid&15 owns codes {ch*128 + tx*8 + j}. All codes int8 in smem.
// NO occupancy cap: scan state (~130 regs) must stay register-resident.
// ---------------------------------------------------------------------------
__global__ __launch_bounds__(256)
void vq_kernel(const float* __restrict__ x,
               const float* __restrict__ cb,
               float* __restrict__ out_q,
               float* __restrict__ out_idx) {
    extern __shared__ char smem[];
    const u32 sb  = smem_u32(smem);
    const int tid = threadIdx.x;
    const int t0  = blockIdx.x * BT;

    u32*   cqp   = (u32*)(smem + SM_CQ);
    u32*   xqp   = (u32*)(smem + SM_XQ);
    int*   colm1 = (int*)(smem + SM_M1);
    int*   colm2 = (int*)(smem + SM_M2);
    int*   coli1 = (int*)(smem + SM_I1);
    float* sc2s  = (float*)(smem + SM_SC2);
    int*   Ms    = (int*)(smem + SM_MS);
    float* sxs   = (float*)(smem + SM_SX);
    int*   bidx  = (int*)(smem + SM_BIDX);
    u64*   part  = (u64*)(smem + SM_PART);

    // Codes gmem->smem (64 KB, async; L2-resident after first wave)
    for (u32 off = tid * 16; off < 16 * NCODES * 4; off += 256 * 16)
        cp16(sb + SM_CQ + off, (const char*)g_cq + off);
    CP_COMMIT();

    for (int i = tid; i < NCODES; i += 256) sc2s[i] = g_sumc2[i];

    // Per-token prologue (tid < 128): stats + quantize + sound margin
    if (tid < BT) {
        const float* xr = x + (size_t)(t0 + tid) * D;
        float xmax = 1e-30f, s1 = 0.f, sx = 0.f;
#pragma unroll 16
        for (int d = 0; d < D; d++) {
            float v = xr[d];
            sx = fmaf(v, v, sx);              // reference-order sum(x^2)
            float a = fabsf(v);
            xmax = fmaxf(xmax, a);
            s1 += a;
        }
        sxs[tid] = sx;
        const float s_x = xmax / 127.f;
        const float inv = 127.f / xmax;
#pragma unroll
        for (int g = 0; g < 16; g++) {
            xqp[g * BT + tid] = pack4(
                clamp127(__float2int_rn(xr[4 * g + 0] * inv)),
                clamp127(__float2int_rn(xr[4 * g + 1] * inv)),
                clamp127(__float2int_rn(xr[4 * g + 2] * inv)),
                clamp127(__float2int_rn(xr[4 * g + 3] * inv)));
        }
        // e_q >= |dot - s_x*s_c*acc|; margin span = sc2span + 4*e_q + fp32 skew
        float e_q    = 0.5f * SC_VAL * s1 + 0.5f * s_x * g_sacmax
                     + 16.f * s_x * SC_VAL;
        float M_dist = g_sc2span + 4.f * e_q + 4e-5f;
        Ms[tid] = (int)ceilf(M_dist / (2.f * s_x * SC_VAL)) + 8;
    }
    CP_WAIT0();
    __syncthreads();

    const int ty = tid >> 4, tx = tid & 15;

    int m1[8], m2[8], i1[8];
#pragma unroll
    for (int i = 0; i < 8; i++) { m1[i] = INT_MIN; m2[i] = INT_MIN; i1[i] = 0; }

    for (int ch = 0; ch < 8; ch++) {
        const int cb0 = ch * 128 + tx * 8;
        int acc[8][8];
#pragma unroll
        for (int i = 0; i < 8; i++)
#pragma unroll
            for (int j = 0; j < 8; j++) acc[i][j] = 0;

#pragma unroll
        for (int g = 0; g < 16; g++) {
            uint4 xa0 = *(uint4*)&xqp[g * BT + ty * 8];
            uint4 xa1 = *(uint4*)&xqp[g * BT + ty * 8 + 4];
            uint4 cv0 = *(uint4*)&cqp[g * NCODES + cb0];
            uint4 cv1 = *(uint4*)&cqp[g * NCODES + cb0 + 4];
            u32 xa[8] = {xa0.x, xa0.y, xa0.z, xa0.w, xa1.x, xa1.y, xa1.z, xa1.w};
            u32 cv[8] = {cv0.x, cv0.y, cv0.z, cv0.w, cv1.x, cv1.y, cv1.z, cv1.w};
#pragma unroll
            for (int i = 0; i < 8; i++)
#pragma unroll
                for (int j = 0; j < 8; j++)
                    acc[i][j] = __dp4a((int)xa[i], (int)cv[j], acc[i][j]);
        }

        // top-2 per token within this thread's column
#pragma unroll
        for (int i = 0; i < 8; i++)
#pragma unroll
            for (int j = 0; j < 8; j++) {
                int v = acc[i][j];
                if (v > m2[i]) {
                    if (v > m1[i]) { m2[i] = m1[i]; m1[i] = v; i1[i] = cb0 + j; }
                    else           { m2[i] = v; }
                }
            }
    }

#pragma unroll
    for (int i = 0; i < 8; i++) {
        const int t = ty * 8 + i;
        colm1[t * 16 + tx] = m1[i];
        colm2[t * 16 + tx] = m2[i];
        coli1[t * 16 + tx] = i1[i];
    }
    __syncthreads();

    // ---- Refinement (token = tid < 128): exact-rescore all codes >= thr ----
    if (tid < BT) {
        const int t = tid;
        int gmax = INT_MIN;
#pragma unroll
        for (int c = 0; c < 16; c++) gmax = max(gmax, colm1[t * 16 + c]);
        const int thr = gmax - Ms[t];

        const float* xr = x + (size_t)(t0 + t) * D;   // L1-hot from prologue
        const float  sx = sxs[t];

        u64 best = 0xFFFFFFFFFFFFFFFFull;
        for (int c = 0; c < 16; c++) {
            if (colm1[t * 16 + c] < thr) continue;
            u64 k1 = exact_key(xr, cb, sc2s, sx, coli1[t * 16 + c]);
            if (k1 < best) best = k1;
            if (colm2[t * 16 + c] >= thr) {
                // Rare: >=2 in-margin codes in this column. Cheap int rescan
                // from smem finds every code with acc >= thr (soundness: any
                // rank-3+ in-margin code implies m2 >= thr, so we land here).
                for (int ch2 = 0; ch2 < 8; ch2++) {
                    const int kb = ch2 * 128 + c * 8;
                    int aj[8];
#pragma unroll
                    for (int j = 0; j < 8; j++) aj[j] = 0;
#pragma unroll
                    for (int g = 0; g < 16; g++) {
                        const int xv = (int)xqp[g * BT + t];
#pragma unroll
                        for (int j = 0; j < 8; j++)
                            aj[j] = __dp4a(xv, (int)cqp[g * NCODES + kb + j], aj[j]);
                    }
#pragma unroll
                    for (int j = 0; j < 8; j++)
                        if (aj[j] >= thr) {
                            u64 k2 = exact_key(xr, cb, sc2s, sx, kb + j);
                            if (k2 < best) best = k2;
                        }
                }
            }
        }

        const int   besti = (int)(best & 0xFFFFFFFFull);
        const float bestd = __uint_as_float((u32)(best >> 32));
        bidx[t] = besti;
        out_idx[t0 + t] = (float)besti;
        part[t] = (u64)llrintf(bestd * 1073741824.f);   // Q30 fixed point
    }
    __syncthreads();

    if (tid == 0) {
        u64 s = 0;
        for (int k = 0; k < BT; k++) s += part[k];
        g_block_loss[blockIdx.x] = s;                   // fresh write: deterministic
    }

    // Quantized output, coalesced; straight-through rounding x + (q - x)
    for (int idx = tid; idx < BT * D; idx += 256) {
        int t = idx >> 6, d = idx & 63;
        float q  = __ldg(&cb[(size_t)bidx[t] * D + d]);
        float xv = x[(size_t)(t0 + t) * D + d];
        out_q[(size_t)(t0 + t) * D + d] = xv + (q - xv);
    }
}

// ---------------------------------------------------------------------------
// Finalize: loss = m + 0.25*m, m = mean(best_dist) over N*D elements
// ---------------------------------------------------------------------------
__global__ void finalize_kernel(float* __restrict__ out_loss, double inv_count) {
    __shared__ u64 sh[256];
    u64 s = 0;
    for (int i = threadIdx.x; i < NBLOCKS; i += 256) s += g_block_loss[i];
    sh[threadIdx.x] = s;
    __syncthreads();
    for (int st = 128; st > 0; st >>= 1) {
        if (threadIdx.x < st) sh[threadIdx.x] += sh[threadIdx.x + st];
        __syncthreads();
    }
    if (threadIdx.x == 0) {
        double tot = (double)sh[0] * (1.0 / 1073741824.0);
        float  m   = (float)(tot * inv_count);
        out_loss[0] = m + 0.25f * m;
    }
}

extern "C" void kernel_launch(void* const* d_in, const int* in_sizes, int n_in,
                              void* d_out, int out_size) {
    const float* x  = (const float*)d_in[0];
    const float* cb = (const float*)d_in[1];
    float* out = (float*)d_out;

    const int n = in_sizes[0] / D;            // 262144 tokens
    float* out_q    = out;
    float* out_loss = out + (size_t)n * D;
    float* out_idx  = out_loss + 1;

    cudaFuncSetAttribute(vq_kernel, cudaFuncAttributeMaxDynamicSharedMemorySize,
                         SMEM_TOTAL);

    prep_kernel<<<8, 128>>>(cb);
    prep2_kernel<<<1, 256>>>();
    vq_kernel<<<n / BT, 256, SMEM_TOTAL>>>(x, cb, out_q, out_idx);
    finalize_kernel<<<1, 256>>>(out_loss, 1.0 / ((double)n * D));
}

// round 17
// speedup vs baseline: 17.3624x; 1.4733x over previous
#include <cuda_runtime.h>
#include <cstdint>

// VQ-VAE quantizer — bit-exact fp32 GEMM scan (round-4 engine, rel_err = 0.0),
// with overheads removed: parallel prep (grid 8) and finalize fused into the
// main kernel via a deterministic last-block reduction.
//
// Measured chip model (R4..R16): one math pipe @16 MAC/cyc/SMSP serves FFMA,
// f32x2, IMAD, dp4a, fp16 and emulated mma.sync alike -> scan wall ~880 us.
// This kernel sits at that wall and trims everything else.

typedef unsigned long long u64;
typedef unsigned int u32;

#define D        64
#define NCODES   1024
#define BT       128          // tokens per block
#define BC       128          // codes per chunk
#define NCHUNK   (NCODES / BC)
#define NBLOCKS  2048
#define STRIDE   132          // padded smem row stride (floats)

// float-index offsets into dynamic smem
#define OFF_AS    0                          // As: [d][token]  64*132
#define OFF_BS    (D * STRIDE)               // Bs: [d][code]   64*132
#define OFF_SUMX2 (OFF_BS + D * STRIDE)      // 128
#define OFF_SC2   (OFF_SUMX2 + BT)           // 128
#define OFF_REDK  (OFF_SC2 + BC)             // u64[128][16] = 4096 float slots (8B aligned)
#define OFF_BIDX  (OFF_REDK + BT * 16 * 2)   // 128
#define OFF_PART  (OFF_BIDX + BT)            // u64[128] (8B aligned)
#define OFF_RED   (OFF_PART + 2 * BT)        // u64[256] last-block reduction scratch
#define SMEM_BYTES ((OFF_RED + 2 * 256) * 4) // 88576 B

__device__ float g_ct[D * NCODES];            // codebook transposed: [d][k]
__device__ float g_sumc2[NCODES];
__device__ u64   g_block_loss[NBLOCKS];
__device__ u32   g_done;

__device__ __forceinline__ void ffma2(u64& acc, u64 a, u64 b) {
    asm("fma.rn.f32x2 %0, %1, %2, %0;" : "+l"(acc) : "l"(a), "l"(b));
}
__device__ __forceinline__ u64 splat2(float v) {
    u64 r;
    asm("mov.b64 %0, {%1, %1};" : "=l"(r) : "f"(v));
    return r;
}
__device__ __forceinline__ void unpack2(u64 p, float& lo, float& hi) {
    asm("mov.b64 {%0, %1}, %2;" : "=f"(lo), "=f"(hi) : "l"(p));
}
__device__ __forceinline__ u64 make_key(float dist, int idx) {
    u64 k;
    asm("mov.b64 %0, {%1, %2};" : "=l"(k) : "r"(idx), "r"(__float_as_uint(dist)));
    return k;   // high word = dist bits (dist >= 0 -> monotone), low word = index
}

// ---------------------------------------------------------------------------
// Prep (8 x 128): transpose codebook, ||c||^2 (reference-order fma), reset flag.
// ---------------------------------------------------------------------------
__global__ void prep_kernel(const float* __restrict__ codebook) {
    const int k = blockIdx.x * 128 + threadIdx.x;
    if (k == 0) g_done = 0u;
    float s = 0.f;
#pragma unroll 8
    for (int d = 0; d < D; d++) {
        float v = codebook[(size_t)k * D + d];
        s = fmaf(v, v, s);
        g_ct[d * NCODES + k] = v;
    }
    g_sumc2[k] = s;
}

// ---------------------------------------------------------------------------
// Main kernel: 256 threads, 128 tokens/block, 8 tokens x 8 codes per thread.
// Exact fp32 distances for ALL codes (no margins): argmin/loss/quantized are
// bit-identical to the reference by construction. Last block folds the loss.
// ---------------------------------------------------------------------------
__global__ __launch_bounds__(256, 2)
void vq_kernel(const float* __restrict__ x,
               const float* __restrict__ codebook,
               float* __restrict__ out_q,
               float* __restrict__ out_loss,
               float* __restrict__ out_idx,
               double inv_count) {
    extern __shared__ float smem[];
    float* As    = smem + OFF_AS;
    float* Bs    = smem + OFF_BS;
    float* sumx2 = smem + OFF_SUMX2;
    float* sc2   = smem + OFF_SC2;
    u64*   redk  = (u64*)(smem + OFF_REDK);
    int*   bidx  = (int*)(smem + OFF_BIDX);
    u64*   part  = (u64*)(smem + OFF_PART);
    u64*   redu  = (u64*)(smem + OFF_RED);

    const int tid = threadIdx.x;
    const int t0  = blockIdx.x * BT;

    // Token tile, transposed into smem (global reads coalesced).
    for (int idx = tid; idx < BT * D; idx += 256) {
        int t = idx >> 6, d = idx & 63;
        As[d * STRIDE + t] = x[(size_t)(t0 + t) * D + d];
    }
    __syncthreads();

    // ||x||^2 per token (sequential over d -> reference rounding class)
    if (tid < BT) {
        float s = 0.f;
#pragma unroll 8
        for (int d = 0; d < D; d++) {
            float v = As[d * STRIDE + tid];
            s = fmaf(v, v, s);
        }
        sumx2[tid] = s;
    }
    __syncthreads();

    const int ty = tid >> 4;   // token group (8 tokens)
    const int tx = tid & 15;   // code group  (8 codes)

    u64 bestk = 0xFFFFFFFFFFFFFFFFull;   // valid only for tid < BT (token tid)

    for (int ch = 0; ch < NCHUNK; ch++) {
        const int c0 = ch * BC;

        // Code chunk (pre-transposed -> coalesced, conflict-free)
        for (int idx = tid; idx < BC * D; idx += 256) {
            int d = idx >> 7, c = idx & 127;
            Bs[d * STRIDE + c] = g_ct[d * NCODES + c0 + c];
        }
        if (tid < BC) sc2[tid] = g_sumc2[c0 + tid];
        __syncthreads();

        // acc2[i][j2]: packed fp32 pair over codes (2*j2, 2*j2+1), token i
        u64 acc2[8][4];
#pragma unroll
        for (int i = 0; i < 8; i++)
#pragma unroll
            for (int j = 0; j < 4; j++) acc2[i][j] = 0ull;

#pragma unroll 2
        for (int d = 0; d < D; d++) {
            const float4 a0 = *(const float4*)&As[d * STRIDE + ty * 8];
            const float4 a1 = *(const float4*)&As[d * STRIDE + ty * 8 + 4];
            const ulonglong2 bA = *(const ulonglong2*)&Bs[d * STRIDE + tx * 8];
            const ulonglong2 bB = *(const ulonglong2*)&Bs[d * STRIDE + tx * 8 + 4];
            const u64 b[4] = {bA.x, bA.y, bB.x, bB.y};
            u64 as_[8];
            as_[0] = splat2(a0.x); as_[1] = splat2(a0.y);
            as_[2] = splat2(a0.z); as_[3] = splat2(a0.w);
            as_[4] = splat2(a1.x); as_[5] = splat2(a1.y);
            as_[6] = splat2(a1.z); as_[7] = splat2(a1.w);
#pragma unroll
            for (int i = 0; i < 8; i++)
#pragma unroll
                for (int j = 0; j < 4; j++)
                    ffma2(acc2[i][j], as_[i], b[j]);
        }

        // Per-thread argmin over its 8 codes, per token row, as 64-bit min-keys.
#pragma unroll
        for (int i = 0; i < 8; i++) {
            const float sxi = sumx2[ty * 8 + i];
            u64 bk = 0xFFFFFFFFFFFFFFFFull;
#pragma unroll
            for (int j = 0; j < 4; j++) {
                float mlo, mhi;
                unpack2(acc2[i][j], mlo, mhi);
                const int cidx = c0 + tx * 8 + 2 * j;
                // dist = fp32((sumx2 + sumc2) - 2*dot): one add, one fused fma
                float dlo = fmaf(-2.f, mlo, sxi + sc2[tx * 8 + 2 * j]);
                float dhi = fmaf(-2.f, mhi, sxi + sc2[tx * 8 + 2 * j + 1]);
                u64 klo = make_key(dlo, cidx);
                u64 khi = make_key(dhi, cidx + 1);
                if (klo < bk) bk = klo;
                if (khi < bk) bk = khi;
            }
            redk[(ty * 8 + i) * 16 + tx] = bk;
        }
        __syncthreads();

        // Cross-thread reduce: min over keys (order-independent, exact tie-break)
        if (tid < BT) {
#pragma unroll
            for (int s = 0; s < 16; s++) {
                u64 k = redk[tid * 16 + s];
                if (k < bestk) bestk = k;
            }
        }
        __syncthreads();
    }

    // Epilogue
    if (tid < BT) {
        const int   besti = (int)(bestk & 0xFFFFFFFFull);
        const float bestd = __uint_as_float((unsigned)(bestk >> 32));
        bidx[tid] = besti;
        out_idx[t0 + tid] = (float)besti;
        part[tid] = (u64)llrintf(bestd * 1073741824.f);   // Q30 fixed point
    }
    __syncthreads();
    if (tid == 0) {
        u64 s = 0;
        for (int i = 0; i < BT; i++) s += part[i];
        g_block_loss[blockIdx.x] = s;                     // fresh write each launch
    }

    // Quantized output, coalesced; straight-through rounding x + (q - x)
    for (int idx = tid; idx < BT * D; idx += 256) {
        int t = idx >> 6, d = idx & 63;
        float q  = __ldg(&codebook[(size_t)bidx[t] * D + d]);
        float xv = x[(size_t)(t0 + t) * D + d];
        out_q[(size_t)(t0 + t) * D + d] = xv + (q - xv);
    }

    // ---- Fused finalize: last block to finish reduces all block losses ----
    __threadfence();
    __shared__ u32 is_last;
    if (tid == 0) is_last = (atomicAdd(&g_done, 1u) == NBLOCKS - 1u) ? 1u : 0u;
    __syncthreads();
    if (is_last) {
        u64 s = 0;
        for (int i = tid; i < NBLOCKS; i += 256) s += g_block_loss[i];
        redu[tid] = s;
        __syncthreads();
        for (int st = 128; st > 0; st >>= 1) {
            if (tid < st) redu[tid] += redu[tid + st];
            __syncthreads();
        }
        if (tid == 0) {
            double tot = (double)redu[0] * (1.0 / 1073741824.0);
            float  m   = (float)(tot * inv_count);
            out_loss[0] = m + 0.25f * m;                  // q_loss + 0.25*e_loss
        }
    }
}

extern "C" void kernel_launch(void* const* d_in, const int* in_sizes, int n_in,
                              void* d_out, int out_size) {
    const float* x  = (const float*)d_in[0];
    const float* cb = (const float*)d_in[1];
    float* out = (float*)d_out;

    const int n = in_sizes[0] / D;            // 262144 tokens
    float* out_q    = out;
    float* out_loss = out + (size_t)n * D;
    float* out_idx  = out_loss + 1;

    cudaFuncSetAttribute(vq_kernel, cudaFuncAttributeMaxDynamicSharedMemorySize,
                         SMEM_BYTES);

    prep_kernel<<<NCODES / 128, 128>>>(cb);
    vq_kernel<<<n / BT, 256, SMEM_BYTES>>>(x, cb, out_q, out_loss, out_idx,
                                           1.0 / ((double)n * D));
}